// round 2
// baseline (speedup 1.0000x reference)
#include <cuda_runtime.h>
#include <cuda_bf16.h>
#include <math.h>

// Problem constants
#define BATCH 8
#define SEQ   2048
#define FDIM  128
#define WDIM  64
#define MROWS (BATCH * SEQ)   // 16384

// Scratch for projected Q, K, V (device globals: allocation-free rule)
__device__ float g_Q[MROWS * WDIM];   // 4 MB
__device__ float g_K[MROWS * WDIM];   // 4 MB
__device__ float g_V[MROWS * FDIM];   // 8 MB

// ---------------------------------------------------------------------------
// Projection GEMM: C[M, Nout] = A[M,128] @ B[128, Nout], row-major.
// 64x64 tile per CTA, 256 threads, 4x4 register fragment per thread.
// ---------------------------------------------------------------------------
__global__ __launch_bounds__(256) void proj_kernel(const float* __restrict__ A,
                                                   const float* __restrict__ Bm,
                                                   float* __restrict__ C,
                                                   int Nout) {
    __shared__ float sA[64][65];
    __shared__ float sB[64][65];

    const int tid = threadIdx.x;
    const int ty = tid >> 4;          // 0..15
    const int tx = tid & 15;          // 0..15
    const int r0 = ty * 4;
    const int c0 = tx * 4;
    const int blockRow = blockIdx.x * 64;
    const int blockCol = blockIdx.y * 64;

    float acc[4][4] = {};

    for (int kk = 0; kk < 128; kk += 64) {
        // Load A tile [64 rows x 64 k]
        #pragma unroll
        for (int i = 0; i < 16; ++i) {
            int e = i * 256 + tid;
            int row = e >> 6, col = e & 63;
            sA[row][col] = A[(blockRow + row) * 128 + kk + col];
        }
        // Load B tile [64 k x 64 cols]
        #pragma unroll
        for (int i = 0; i < 16; ++i) {
            int e = i * 256 + tid;
            int row = e >> 6, col = e & 63;
            sB[row][col] = Bm[(kk + row) * Nout + blockCol + col];
        }
        __syncthreads();

        #pragma unroll 8
        for (int k = 0; k < 64; ++k) {
            float a[4], b[4];
            #pragma unroll
            for (int i = 0; i < 4; ++i) a[i] = sA[r0 + i][k];
            #pragma unroll
            for (int j = 0; j < 4; ++j) b[j] = sB[k][c0 + j];
            #pragma unroll
            for (int i = 0; i < 4; ++i)
                #pragma unroll
                for (int j = 0; j < 4; ++j)
                    acc[i][j] = fmaf(a[i], b[j], acc[i][j]);
        }
        __syncthreads();
    }

    #pragma unroll
    for (int i = 0; i < 4; ++i)
        #pragma unroll
        for (int j = 0; j < 4; ++j)
            C[(blockRow + r0 + i) * Nout + blockCol + c0 + j] = acc[i][j];
}

// ---------------------------------------------------------------------------
// Fused flash-attention (fp32 SIMT):
// grid = (SEQ/64, BATCH), 256 threads/CTA. Each CTA: 64 query rows.
// Online softmax over 32 KV tiles of 64.
// ---------------------------------------------------------------------------
#define SMEM_FLOATS (64*65*3 + 64*128 + 64*3)

__global__ __launch_bounds__(256, 2) void attn_kernel(const float* __restrict__ Qg,
                                                      const float* __restrict__ Kg,
                                                      const float* __restrict__ Vg,
                                                      float* __restrict__ outg) {
    extern __shared__ float sm[];
    float* sQ = sm;                       // [64][65]
    float* sK = sQ + 64 * 65;             // [64][65]
    float* sS = sK + 64 * 65;             // [64][65]
    float* sV = sS + 64 * 65;             // [64][128]
    float* sM = sV + 64 * 128;            // [64]
    float* sL = sM + 64;                  // [64]
    float* sScale = sL + 64;              // [64]

    const int tid = threadIdx.x;
    const int ty = tid >> 4;              // 0..15
    const int tx = tid & 15;              // 0..15
    const int r0 = ty * 4;                // S/O row base (4 rows)
    const int c0s = tx * 4;               // S col base (4 cols)
    const int c0o = tx * 8;               // O col base (8 cols)

    const int b = blockIdx.y;
    const int q0 = blockIdx.x * 64;

    const float* Qb = Qg + (size_t)b * SEQ * WDIM;
    const float* Kb = Kg + (size_t)b * SEQ * WDIM;
    const float* Vb = Vg + (size_t)b * SEQ * FDIM;
    float* outb = outg + (size_t)b * SEQ * FDIM;

    // Load Q tile [64 x 64]
    #pragma unroll
    for (int i = 0; i < 16; ++i) {
        int e = i * 256 + tid;
        int row = e >> 6, col = e & 63;
        sQ[row * 65 + col] = Qb[(q0 + row) * WDIM + col];
    }
    if (tid < 64) {
        sM[tid] = -INFINITY;
        sL[tid] = 0.0f;
    }

    float o[4][8] = {};

    for (int kt = 0; kt < SEQ / 64; ++kt) {
        const int kv0 = kt * 64;
        // Load K tile [64 x 64]
        #pragma unroll
        for (int i = 0; i < 16; ++i) {
            int e = i * 256 + tid;
            int row = e >> 6, col = e & 63;
            sK[row * 65 + col] = Kb[(kv0 + row) * WDIM + col];
        }
        // Load V tile [64 x 128]
        #pragma unroll
        for (int i = 0; i < 32; ++i) {
            int e = i * 256 + tid;
            int row = e >> 7, col = e & 127;
            sV[row * 128 + col] = Vb[(kv0 + row) * FDIM + col];
        }
        __syncthreads();

        // S = Q K^T (4x4 fragment)
        float acc[4][4] = {};
        #pragma unroll 4
        for (int k = 0; k < 64; ++k) {
            float q[4], kv[4];
            #pragma unroll
            for (int i = 0; i < 4; ++i) q[i] = sQ[(r0 + i) * 65 + k];
            #pragma unroll
            for (int j = 0; j < 4; ++j) kv[j] = sK[(c0s + j) * 65 + k];
            #pragma unroll
            for (int i = 0; i < 4; ++i)
                #pragma unroll
                for (int j = 0; j < 4; ++j)
                    acc[i][j] = fmaf(q[i], kv[j], acc[i][j]);
        }
        #pragma unroll
        for (int i = 0; i < 4; ++i)
            #pragma unroll
            for (int j = 0; j < 4; ++j)
                sS[(r0 + i) * 65 + c0s + j] = acc[i][j];
        __syncthreads();

        // Online softmax: 4 threads per row, each covers 16 columns
        {
            const int row = tid >> 2;
            const int seg = tid & 3;
            const int base = seg * 16;
            float* srow = sS + row * 65 + base;

            float mloc = -INFINITY;
            #pragma unroll
            for (int t = 0; t < 16; ++t) mloc = fmaxf(mloc, srow[t]);
            mloc = fmaxf(mloc, __shfl_xor_sync(0xffffffffu, mloc, 1));
            mloc = fmaxf(mloc, __shfl_xor_sync(0xffffffffu, mloc, 2));

            const float mold = sM[row];
            const float mnew = fmaxf(mold, mloc);

            float lloc = 0.0f;
            #pragma unroll
            for (int t = 0; t < 16; ++t) {
                float p = __expf(srow[t] - mnew);
                srow[t] = p;
                lloc += p;
            }
            lloc += __shfl_xor_sync(0xffffffffu, lloc, 1);
            lloc += __shfl_xor_sync(0xffffffffu, lloc, 2);

            if (seg == 0) {
                const float scale = __expf(mold - mnew);
                sM[row] = mnew;
                sL[row] = sL[row] * scale + lloc;
                sScale[row] = scale;
            }
        }
        __syncthreads();

        // O = O * scale + P @ V
        #pragma unroll
        for (int i = 0; i < 4; ++i) {
            const float sc = sScale[r0 + i];
            #pragma unroll
            for (int j = 0; j < 8; ++j) o[i][j] *= sc;
        }
        #pragma unroll 2
        for (int m = 0; m < 64; ++m) {
            float p[4];
            #pragma unroll
            for (int i = 0; i < 4; ++i) p[i] = sS[(r0 + i) * 65 + m];
            const float4 v0 = *reinterpret_cast<const float4*>(&sV[m * 128 + c0o]);
            const float4 v1 = *reinterpret_cast<const float4*>(&sV[m * 128 + c0o + 4]);
            #pragma unroll
            for (int i = 0; i < 4; ++i) {
                o[i][0] = fmaf(p[i], v0.x, o[i][0]);
                o[i][1] = fmaf(p[i], v0.y, o[i][1]);
                o[i][2] = fmaf(p[i], v0.z, o[i][2]);
                o[i][3] = fmaf(p[i], v0.w, o[i][3]);
                o[i][4] = fmaf(p[i], v1.x, o[i][4]);
                o[i][5] = fmaf(p[i], v1.y, o[i][5]);
                o[i][6] = fmaf(p[i], v1.z, o[i][6]);
                o[i][7] = fmaf(p[i], v1.w, o[i][7]);
            }
        }
        __syncthreads();   // sS/sV reused next tile
    }

    // Finalize: divide by l and store
    #pragma unroll
    for (int i = 0; i < 4; ++i) {
        const float inv = 1.0f / sL[r0 + i];
        float4 w0, w1;
        w0.x = o[i][0] * inv; w0.y = o[i][1] * inv;
        w0.z = o[i][2] * inv; w0.w = o[i][3] * inv;
        w1.x = o[i][4] * inv; w1.y = o[i][5] * inv;
        w1.z = o[i][6] * inv; w1.w = o[i][7] * inv;
        float* dst = &outb[(q0 + r0 + i) * FDIM + c0o];
        *reinterpret_cast<float4*>(dst) = w0;
        *reinterpret_cast<float4*>(dst + 4) = w1;
    }
}

// ---------------------------------------------------------------------------
extern "C" void kernel_launch(void* const* d_in, const int* in_sizes, int n_in,
                              void* d_out, int out_size) {
    const float* x  = (const float*)d_in[0];
    // d_in[1] = adj (bool), unused by the reference math
    const float* wk = (const float*)d_in[2];
    const float* wv = (const float*)d_in[3];
    const float* wq = (const float*)d_in[4];
    float* out = (float*)d_out;

    void *pQ, *pK, *pV;
    cudaGetSymbolAddress(&pQ, g_Q);
    cudaGetSymbolAddress(&pK, g_K);
    cudaGetSymbolAddress(&pV, g_V);

    const int smem_bytes = SMEM_FLOATS * (int)sizeof(float);
    cudaFuncSetAttribute(attn_kernel, cudaFuncAttributeMaxDynamicSharedMemorySize,
                         smem_bytes);

    // Projections
    proj_kernel<<<dim3(MROWS / 64, WDIM / 64), 256>>>(x, wk, (float*)pK, WDIM);
    proj_kernel<<<dim3(MROWS / 64, WDIM / 64), 256>>>(x, wq, (float*)pQ, WDIM);
    proj_kernel<<<dim3(MROWS / 64, FDIM / 64), 256>>>(x, wv, (float*)pV, FDIM);

    // Fused attention
    attn_kernel<<<dim3(SEQ / 64, BATCH), 256, smem_bytes>>>(
        (const float*)pQ, (const float*)pK, (const float*)pV, out);
}

// round 4
// speedup vs baseline: 1.4526x; 1.4526x over previous
#include <cuda_runtime.h>
#include <cuda_bf16.h>
#include <math.h>

// Problem constants
#define BATCH 8
#define SEQ   2048
#define FDIM  128
#define WDIM  64
#define MROWS (BATCH * SEQ)   // 16384

// Scratch for projected Q, K, V (device globals: allocation-free rule)
__device__ float g_Q[MROWS * WDIM];   // 4 MB
__device__ float g_K[MROWS * WDIM];   // 4 MB
__device__ float g_V[MROWS * FDIM];   // 8 MB

// ---------------------------------------------------------------------------
// Fused projection GEMMs. grid = (MROWS/64, 4):
//   y=0: K = x @ w_key   [.., 64]
//   y=1: Q = x @ w_query [.., 64]
//   y=2: V cols 0..63    = x @ w_value[:, 0:64]
//   y=3: V cols 64..127  = x @ w_value[:, 64:128]
// 64x64 tile, 256 threads, 4x4 fragments.
// ---------------------------------------------------------------------------
__global__ __launch_bounds__(256) void proj_fused_kernel(
    const float* __restrict__ x,
    const float* __restrict__ wk,
    const float* __restrict__ wq,
    const float* __restrict__ wv,
    float* __restrict__ Kout,
    float* __restrict__ Qout,
    float* __restrict__ Vout) {
    __shared__ float sA[64][65];
    __shared__ float sB[64][65];

    const int which = blockIdx.y;
    const float* Bm;
    float* C;
    int Nout, colBase;
    if (which == 0)      { Bm = wk; C = Kout; Nout = 64;  colBase = 0;  }
    else if (which == 1) { Bm = wq; C = Qout; Nout = 64;  colBase = 0;  }
    else if (which == 2) { Bm = wv; C = Vout; Nout = 128; colBase = 0;  }
    else                 { Bm = wv; C = Vout; Nout = 128; colBase = 64; }

    const int tid = threadIdx.x;
    const int ty = tid >> 4;
    const int tx = tid & 15;
    const int r0 = ty * 4;
    const int c0 = tx * 4;
    const int blockRow = blockIdx.x * 64;

    float acc[4][4] = {};

    for (int kk = 0; kk < 128; kk += 64) {
        #pragma unroll
        for (int i = 0; i < 16; ++i) {
            int e = i * 256 + tid;
            int row = e >> 6, col = e & 63;
            sA[row][col] = x[(blockRow + row) * 128 + kk + col];
        }
        #pragma unroll
        for (int i = 0; i < 16; ++i) {
            int e = i * 256 + tid;
            int row = e >> 6, col = e & 63;
            sB[row][col] = Bm[(kk + row) * Nout + colBase + col];
        }
        __syncthreads();

        #pragma unroll 8
        for (int k = 0; k < 64; ++k) {
            float a[4], b[4];
            #pragma unroll
            for (int i = 0; i < 4; ++i) a[i] = sA[r0 + i][k];
            #pragma unroll
            for (int j = 0; j < 4; ++j) b[j] = sB[k][c0 + j];
            #pragma unroll
            for (int i = 0; i < 4; ++i)
                #pragma unroll
                for (int j = 0; j < 4; ++j)
                    acc[i][j] = fmaf(a[i], b[j], acc[i][j]);
        }
        __syncthreads();
    }

    #pragma unroll
    for (int i = 0; i < 4; ++i)
        #pragma unroll
        for (int j = 0; j < 4; ++j)
            C[(blockRow + r0 + i) * Nout + colBase + c0 + j] = acc[i][j];
}

// ---------------------------------------------------------------------------
// Fused flash-attention, fp32 SIMT, 8x8 register fragments.
// grid = (SEQ/128, BATCH) = (16, 8), 256 threads.
// CTA tile: 128 q-rows; KV tiles of 128. Softmax fully in registers
// (row = 16-lane shfl group). P hits smem exactly once.
// ---------------------------------------------------------------------------
#define SQ_STRIDE  68    // sQ  [128][64]  + pad (float4-aligned)
#define SKT_STRIDE 132   // sKT [64][128]  (K transposed: [w][kv]) + pad
#define SV_STRIDE  132   // sV  [128][128] + pad
#define SP_STRIDE  132   // sP  [128][128] + pad
#define ATTN_SMEM_FLOATS (128*SQ_STRIDE + 64*SKT_STRIDE + 128*SV_STRIDE + 128*SP_STRIDE)

__global__ __launch_bounds__(256, 1) void attn_kernel(const float* __restrict__ Qg,
                                                      const float* __restrict__ Kg,
                                                      const float* __restrict__ Vg,
                                                      float* __restrict__ outg) {
    extern __shared__ float sm[];
    float* sQ  = sm;
    float* sKT = sQ  + 128 * SQ_STRIDE;
    float* sV  = sKT + 64  * SKT_STRIDE;
    float* sP  = sV  + 128 * SV_STRIDE;

    const int tid = threadIdx.x;
    const int ty = tid >> 4;      // 0..15 -> q-row group
    const int tx = tid & 15;      // 0..15 -> col group
    const int r0 = ty * 8;
    const int c0 = tx * 8;

    const int b = blockIdx.y;
    const int q0 = blockIdx.x * 128;

    const float* Qb = Qg + (size_t)b * SEQ * WDIM;
    const float* Kb = Kg + (size_t)b * SEQ * WDIM;
    const float* Vb = Vg + (size_t)b * SEQ * FDIM;
    float* outb = outg + (size_t)b * SEQ * FDIM;

    // Load Q tile [128 x 64]
    #pragma unroll
    for (int i = 0; i < 8; ++i) {
        int e = i * 256 + tid;            // 0..2047 float4s
        int row = e >> 4;
        int w4 = (e & 15) * 4;
        *reinterpret_cast<float4*>(&sQ[row * SQ_STRIDE + w4]) =
            *reinterpret_cast<const float4*>(&Qb[(q0 + row) * WDIM + w4]);
    }

    float m_run[8], l_run[8];
    #pragma unroll
    for (int i = 0; i < 8; ++i) { m_run[i] = -INFINITY; l_run[i] = 0.0f; }
    float o[8][8] = {};

    for (int kt = 0; kt < SEQ / 128; ++kt) {
        const int kv0 = kt * 128;
        __syncthreads();   // previous PV finished with sKT/sV

        // Load K tile transposed: sKT[w][kv]
        #pragma unroll
        for (int i = 0; i < 8; ++i) {
            int e = i * 256 + tid;
            int kvr = e >> 4;
            int w4 = (e & 15) * 4;
            float4 kk = *reinterpret_cast<const float4*>(&Kb[(kv0 + kvr) * WDIM + w4]);
            sKT[(w4 + 0) * SKT_STRIDE + kvr] = kk.x;
            sKT[(w4 + 1) * SKT_STRIDE + kvr] = kk.y;
            sKT[(w4 + 2) * SKT_STRIDE + kvr] = kk.z;
            sKT[(w4 + 3) * SKT_STRIDE + kvr] = kk.w;
        }
        // Load V tile [128 x 128]
        #pragma unroll
        for (int i = 0; i < 16; ++i) {
            int e = i * 256 + tid;
            int mrow = e >> 5;
            int f4 = (e & 31) * 4;
            *reinterpret_cast<float4*>(&sV[mrow * SV_STRIDE + f4]) =
                *reinterpret_cast<const float4*>(&Vb[(kv0 + mrow) * FDIM + f4]);
        }
        __syncthreads();

        // ---- S = Q K^T : 8x8 fragment, vectorized over w by 4 ----
        float acc[8][8] = {};
        #pragma unroll 2
        for (int w = 0; w < WDIM; w += 4) {
            float4 q4[8];
            #pragma unroll
            for (int i = 0; i < 8; ++i)
                q4[i] = *reinterpret_cast<const float4*>(&sQ[(r0 + i) * SQ_STRIDE + w]);
            #pragma unroll
            for (int ww = 0; ww < 4; ++ww) {
                const float4 kA = *reinterpret_cast<const float4*>(&sKT[(w + ww) * SKT_STRIDE + c0]);
                const float4 kB = *reinterpret_cast<const float4*>(&sKT[(w + ww) * SKT_STRIDE + c0 + 4]);
                #pragma unroll
                for (int i = 0; i < 8; ++i) {
                    const float qv = (ww == 0) ? q4[i].x : (ww == 1) ? q4[i].y
                                   : (ww == 2) ? q4[i].z : q4[i].w;
                    acc[i][0] = fmaf(qv, kA.x, acc[i][0]);
                    acc[i][1] = fmaf(qv, kA.y, acc[i][1]);
                    acc[i][2] = fmaf(qv, kA.z, acc[i][2]);
                    acc[i][3] = fmaf(qv, kA.w, acc[i][3]);
                    acc[i][4] = fmaf(qv, kB.x, acc[i][4]);
                    acc[i][5] = fmaf(qv, kB.y, acc[i][5]);
                    acc[i][6] = fmaf(qv, kB.z, acc[i][6]);
                    acc[i][7] = fmaf(qv, kB.w, acc[i][7]);
                }
            }
        }

        // ---- Online softmax in registers (reduce across 16 lanes of half-warp) ----
        float mt[8];
        #pragma unroll
        for (int i = 0; i < 8; ++i) {
            float v = acc[i][0];
            #pragma unroll
            for (int j = 1; j < 8; ++j) v = fmaxf(v, acc[i][j]);
            mt[i] = v;
        }
        #pragma unroll
        for (int mask = 1; mask <= 8; mask <<= 1)
            #pragma unroll
            for (int i = 0; i < 8; ++i)
                mt[i] = fmaxf(mt[i], __shfl_xor_sync(0xffffffffu, mt[i], mask));

        float sc[8], mnew[8];
        #pragma unroll
        for (int i = 0; i < 8; ++i) {
            mnew[i] = fmaxf(m_run[i], mt[i]);
            sc[i] = __expf(m_run[i] - mnew[i]);   // first tile: exp(-inf)=0
            m_run[i] = mnew[i];
        }

        float lt[8];
        #pragma unroll
        for (int i = 0; i < 8; ++i) {
            float s = 0.0f;
            #pragma unroll
            for (int j = 0; j < 8; ++j) {
                acc[i][j] = __expf(acc[i][j] - mnew[i]);
                s += acc[i][j];
            }
            lt[i] = s;
        }
        #pragma unroll
        for (int mask = 1; mask <= 8; mask <<= 1)
            #pragma unroll
            for (int i = 0; i < 8; ++i)
                lt[i] += __shfl_xor_sync(0xffffffffu, lt[i], mask);

        #pragma unroll
        for (int i = 0; i < 8; ++i) {
            l_run[i] = l_run[i] * sc[i] + lt[i];
            #pragma unroll
            for (int j = 0; j < 8; ++j) o[i][j] *= sc[i];
        }

        // ---- Store P to smem (single pass) ----
        #pragma unroll
        for (int i = 0; i < 8; ++i) {
            *reinterpret_cast<float4*>(&sP[(r0 + i) * SP_STRIDE + c0]) =
                make_float4(acc[i][0], acc[i][1], acc[i][2], acc[i][3]);
            *reinterpret_cast<float4*>(&sP[(r0 + i) * SP_STRIDE + c0 + 4]) =
                make_float4(acc[i][4], acc[i][5], acc[i][6], acc[i][7]);
        }
        __syncthreads();

        // ---- O += P @ V : 8x8 fragment, vectorized over m by 4 ----
        #pragma unroll 2
        for (int m = 0; m < 128; m += 4) {
            float4 p4[8];
            #pragma unroll
            for (int i = 0; i < 8; ++i)
                p4[i] = *reinterpret_cast<const float4*>(&sP[(r0 + i) * SP_STRIDE + m]);
            #pragma unroll
            for (int mm = 0; mm < 4; ++mm) {
                const float4 vA = *reinterpret_cast<const float4*>(&sV[(m + mm) * SV_STRIDE + c0]);
                const float4 vB = *reinterpret_cast<const float4*>(&sV[(m + mm) * SV_STRIDE + c0 + 4]);
                #pragma unroll
                for (int i = 0; i < 8; ++i) {
                    const float pv = (mm == 0) ? p4[i].x : (mm == 1) ? p4[i].y
                                   : (mm == 2) ? p4[i].z : p4[i].w;
                    o[i][0] = fmaf(pv, vA.x, o[i][0]);
                    o[i][1] = fmaf(pv, vA.y, o[i][1]);
                    o[i][2] = fmaf(pv, vA.z, o[i][2]);
                    o[i][3] = fmaf(pv, vA.w, o[i][3]);
                    o[i][4] = fmaf(pv, vB.x, o[i][4]);
                    o[i][5] = fmaf(pv, vB.y, o[i][5]);
                    o[i][6] = fmaf(pv, vB.z, o[i][6]);
                    o[i][7] = fmaf(pv, vB.w, o[i][7]);
                }
            }
        }
    }

    // Finalize: divide by l, store
    #pragma unroll
    for (int i = 0; i < 8; ++i) {
        const float inv = 1.0f / l_run[i];
        float4 w0, w1;
        w0.x = o[i][0] * inv; w0.y = o[i][1] * inv;
        w0.z = o[i][2] * inv; w0.w = o[i][3] * inv;
        w1.x = o[i][4] * inv; w1.y = o[i][5] * inv;
        w1.z = o[i][6] * inv; w1.w = o[i][7] * inv;
        float* dst = &outb[(q0 + r0 + i) * FDIM + c0];
        *reinterpret_cast<float4*>(dst) = w0;
        *reinterpret_cast<float4*>(dst + 4) = w1;
    }
}

// ---------------------------------------------------------------------------
extern "C" void kernel_launch(void* const* d_in, const int* in_sizes, int n_in,
                              void* d_out, int out_size) {
    const float* x  = (const float*)d_in[0];
    // d_in[1] = adj (bool), unused by the reference math
    const float* wk = (const float*)d_in[2];
    const float* wv = (const float*)d_in[3];
    const float* wq = (const float*)d_in[4];
    float* out = (float*)d_out;

    void *pQ, *pK, *pV;
    cudaGetSymbolAddress(&pQ, g_Q);
    cudaGetSymbolAddress(&pK, g_K);
    cudaGetSymbolAddress(&pV, g_V);

    const int smem_bytes = ATTN_SMEM_FLOATS * (int)sizeof(float);
    cudaFuncSetAttribute(attn_kernel, cudaFuncAttributeMaxDynamicSharedMemorySize,
                         smem_bytes);

    // Fused projections: K, Q, V in one launch
    proj_fused_kernel<<<dim3(MROWS / 64, 4), 256>>>(
        x, wk, wq, wv, (float*)pK, (float*)pQ, (float*)pV);

    // Fused attention
    attn_kernel<<<dim3(SEQ / 128, BATCH), 256, smem_bytes>>>(
        (const float*)pQ, (const float*)pK, (const float*)pV, out);
}

// round 7
// speedup vs baseline: 5.1089x; 3.5171x over previous
#include <cuda_runtime.h>
#include <cuda_fp16.h>
#include <cstdint>
#include <math.h>

// Problem constants
#define BATCH 8
#define SEQ   2048
#define FDIM  128
#define WDIM  64
#define MROWS (BATCH * SEQ)   // 16384

// Scratch (device globals: allocation-free rule)
__device__ __half g_Qh[MROWS * WDIM];
__device__ __half g_Ql[MROWS * WDIM];
__device__ __half g_Kh[MROWS * WDIM];
__device__ __half g_Kl[MROWS * WDIM];
__device__ __half g_Vh[MROWS * FDIM];

// ---------------------------------------------------------------------------
// PTX helpers (ALL baseline ISA: ldmatrix sm_75+, mma sm_80+, cp.async sm_80+)
// ---------------------------------------------------------------------------
__device__ __forceinline__ uint32_t cvta_s(const void* p) {
    uint32_t a;
    asm("{ .reg .u64 t; cvta.to.shared.u64 t, %1; cvt.u32.u64 %0, t; }"
        : "=r"(a) : "l"(p));
    return a;
}
__device__ __forceinline__ void ldsm4(uint32_t addr, uint32_t& r0, uint32_t& r1,
                                      uint32_t& r2, uint32_t& r3) {
    asm volatile("ldmatrix.sync.aligned.m8n8.x4.shared.b16 {%0,%1,%2,%3}, [%4];"
                 : "=r"(r0), "=r"(r1), "=r"(r2), "=r"(r3) : "r"(addr));
}
__device__ __forceinline__ void ldsm4t(uint32_t addr, uint32_t& r0, uint32_t& r1,
                                       uint32_t& r2, uint32_t& r3) {
    asm volatile("ldmatrix.sync.aligned.m8n8.x4.trans.shared.b16 {%0,%1,%2,%3}, [%4];"
                 : "=r"(r0), "=r"(r1), "=r"(r2), "=r"(r3) : "r"(addr));
}
__device__ __forceinline__ void mma_f16(float* c, uint32_t a0, uint32_t a1,
                                        uint32_t a2, uint32_t a3,
                                        uint32_t b0, uint32_t b1) {
    asm volatile(
        "mma.sync.aligned.m16n8k16.row.col.f32.f16.f16.f32 "
        "{%0,%1,%2,%3}, {%4,%5,%6,%7}, {%8,%9}, {%0,%1,%2,%3};"
        : "+f"(c[0]), "+f"(c[1]), "+f"(c[2]), "+f"(c[3])
        : "r"(a0), "r"(a1), "r"(a2), "r"(a3), "r"(b0), "r"(b1));
}
__device__ __forceinline__ void cpa16(uint32_t d, const void* s) {
    asm volatile("cp.async.cg.shared.global [%0], [%1], 16;" :: "r"(d), "l"(s));
}
#define CP_COMMIT() asm volatile("cp.async.commit_group;" ::: "memory")
#define CP_WAIT1()  asm volatile("cp.async.wait_group 1;" ::: "memory")
#define CP_WAIT0()  asm volatile("cp.async.wait_group 0;" ::: "memory")

// ---------------------------------------------------------------------------
// SMEM layout (bytes). Padded strides (in halfs) make ldmatrix conflict-free:
// row stride 72h=144B / 136h=272B -> 8 rows hit 8 distinct 16B bank groups.
// ---------------------------------------------------------------------------
#define QS 72
#define KS 72
#define VS 136
#define SQH_OFF  0
#define SQL_OFF  (128 * QS * 2)             // 18432
#define STAGE_OFF (2 * 128 * QS * 2)        // 36864
#define KH_OFF   0
#define KL_OFF   (128 * KS * 2)             // 18432
#define SV_OFF   (2 * 128 * KS * 2)         // 36864
#define STAGE_SZ (2 * 128 * KS * 2 + 128 * VS * 2)   // 71680
#define ATTN_SMEM (STAGE_OFF + 2 * STAGE_SZ)         // 180224

__device__ __forceinline__ void stage_load(uint32_t base,
                                           const __half* Khb, const __half* Klb,
                                           const __half* Vhb, int kv0, int tid) {
    #pragma unroll
    for (int i = 0; i < 4; ++i) {
        int c = i * 256 + tid;
        int r = c >> 3, c8 = (c & 7) * 8;
        cpa16(base + KH_OFF + (r * KS + c8) * 2, Khb + (size_t)(kv0 + r) * WDIM + c8);
        cpa16(base + KL_OFF + (r * KS + c8) * 2, Klb + (size_t)(kv0 + r) * WDIM + c8);
    }
    #pragma unroll
    for (int i = 0; i < 8; ++i) {
        int c = i * 256 + tid;
        int r = c >> 4, c8 = (c & 15) * 8;
        cpa16(base + SV_OFF + (r * VS + c8) * 2, Vhb + (size_t)(kv0 + r) * FDIM + c8);
    }
}

// ---------------------------------------------------------------------------
// FA2-style fused attention on mma.sync fp16.
// grid = (SEQ/128, BATCH) = (16, 8), 256 threads (8 warps x 16 q-rows).
// ---------------------------------------------------------------------------
__global__ __launch_bounds__(256, 1) void attn_mma_kernel(
    const __half* __restrict__ Qh, const __half* __restrict__ Ql,
    const __half* __restrict__ Kh, const __half* __restrict__ Kl,
    const __half* __restrict__ Vh, float* __restrict__ out) {
    extern __shared__ char smem[];
    const uint32_t sb = cvta_s(smem);
    const int tid = threadIdx.x;
    const int wid = tid >> 5;
    const int lane = tid & 31;
    const int g = lane >> 2;       // row within 8-row group
    const int tig = lane & 3;      // thread-in-group
    const int grp = lane >> 3;     // ldmatrix matrix index
    const int lr = lane & 7;       // ldmatrix row within matrix
    const int wbase = wid * 16;    // this warp's q-row base within CTA

    const int b = blockIdx.y;
    const int q0 = blockIdx.x * 128;
    const __half* Qhb = Qh + ((size_t)b * SEQ + q0) * WDIM;
    const __half* Qlb = Ql + ((size_t)b * SEQ + q0) * WDIM;
    const __half* Khb = Kh + (size_t)b * SEQ * WDIM;
    const __half* Klb = Kl + (size_t)b * SEQ * WDIM;
    const __half* Vhb = Vh + (size_t)b * SEQ * FDIM;
    float* outb = out + ((size_t)b * SEQ + q0) * FDIM;

    // Prologue: Q (group 0), stage 0 (group 1)
    #pragma unroll
    for (int i = 0; i < 4; ++i) {
        int c = i * 256 + tid;
        int r = c >> 3, c8 = (c & 7) * 8;
        cpa16(sb + SQH_OFF + (r * QS + c8) * 2, Qhb + (size_t)r * WDIM + c8);
        cpa16(sb + SQL_OFF + (r * QS + c8) * 2, Qlb + (size_t)r * WDIM + c8);
    }
    CP_COMMIT();
    stage_load(sb + STAGE_OFF, Khb, Klb, Vhb, 0, tid);
    CP_COMMIT();

    // Wait Q (group0 done when <=1 pending), then load Q fragments
    CP_WAIT1();
    __syncthreads();
    uint32_t qh[4][4], ql[4][4];
    #pragma unroll
    for (int kk = 0; kk < 4; ++kk) {
        // M0: rows 0-7 cols 0-7 | M1: rows 8-15 cols 0-7 | M2: rows 0-7 cols 8-15 | M3: rows 8-15 cols 8-15
        uint32_t a = sb + SQH_OFF +
            ((wbase + lr + (grp & 1) * 8) * QS + kk * 16 + (grp >> 1) * 8) * 2;
        ldsm4(a, qh[kk][0], qh[kk][1], qh[kk][2], qh[kk][3]);
        uint32_t al = a + (SQL_OFF - SQH_OFF);
        ldsm4(al, ql[kk][0], ql[kk][1], ql[kk][2], ql[kk][3]);
    }

    float o[16][4];
    #pragma unroll
    for (int nt = 0; nt < 16; ++nt)
        #pragma unroll
        for (int j = 0; j < 4; ++j) o[nt][j] = 0.0f;
    float m0 = -INFINITY, m1 = -INFINITY, l0 = 0.0f, l1 = 0.0f;

    for (int t = 0; t < 16; ++t) {
        if (t + 1 < 16) {
            stage_load(sb + STAGE_OFF + ((t + 1) & 1) * STAGE_SZ,
                       Khb, Klb, Vhb, (t + 1) * 128, tid);
            CP_COMMIT();
            CP_WAIT1();
        } else {
            CP_WAIT0();
        }
        __syncthreads();

        const uint32_t stg = sb + STAGE_OFF + (t & 1) * STAGE_SZ;

        // ---- S = Q K^T (3 fp16 MMAs: hi*hi + hi*lo + lo*hi) ----
        float c[16][4];
        #pragma unroll
        for (int nt = 0; nt < 16; ++nt)
            #pragma unroll
            for (int j = 0; j < 4; ++j) c[nt][j] = 0.0f;

        #pragma unroll
        for (int kk = 0; kk < 4; ++kk) {
            #pragma unroll
            for (int nn2 = 0; nn2 < 8; ++nn2) {
                // K stored n-major [kv][w]; B frags via non-trans ldmatrix
                uint32_t off = (((nn2 * 2 + (grp >> 1)) * 8 + lr) * KS
                                + kk * 16 + (grp & 1) * 8) * 2;
                uint32_t h0, h1, h2, h3, e0, e1, e2, e3;
                ldsm4(stg + KH_OFF + off, h0, h1, h2, h3);
                ldsm4(stg + KL_OFF + off, e0, e1, e2, e3);
                mma_f16(c[2 * nn2],     qh[kk][0], qh[kk][1], qh[kk][2], qh[kk][3], h0, h1);
                mma_f16(c[2 * nn2 + 1], qh[kk][0], qh[kk][1], qh[kk][2], qh[kk][3], h2, h3);
                mma_f16(c[2 * nn2],     qh[kk][0], qh[kk][1], qh[kk][2], qh[kk][3], e0, e1);
                mma_f16(c[2 * nn2 + 1], qh[kk][0], qh[kk][1], qh[kk][2], qh[kk][3], e2, e3);
                mma_f16(c[2 * nn2],     ql[kk][0], ql[kk][1], ql[kk][2], ql[kk][3], h0, h1);
                mma_f16(c[2 * nn2 + 1], ql[kk][0], ql[kk][1], ql[kk][2], ql[kk][3], h2, h3);
            }
        }

        // ---- Online softmax in registers ----
        float mt0 = -INFINITY, mt1 = -INFINITY;
        #pragma unroll
        for (int nt = 0; nt < 16; ++nt) {
            mt0 = fmaxf(mt0, fmaxf(c[nt][0], c[nt][1]));
            mt1 = fmaxf(mt1, fmaxf(c[nt][2], c[nt][3]));
        }
        mt0 = fmaxf(mt0, __shfl_xor_sync(0xffffffffu, mt0, 1));
        mt0 = fmaxf(mt0, __shfl_xor_sync(0xffffffffu, mt0, 2));
        mt1 = fmaxf(mt1, __shfl_xor_sync(0xffffffffu, mt1, 1));
        mt1 = fmaxf(mt1, __shfl_xor_sync(0xffffffffu, mt1, 2));

        const float mn0 = fmaxf(m0, mt0);
        const float mn1 = fmaxf(m1, mt1);
        const float sc0 = __expf(m0 - mn0);   // first tile: exp(-inf) = 0
        const float sc1 = __expf(m1 - mn1);
        m0 = mn0; m1 = mn1;

        // P = exp(S - m), fp16-rounded; l accumulated from the ROUNDED values
        uint32_t p[16][2];
        float lp0 = 0.0f, lp1 = 0.0f;
        #pragma unroll
        for (int nt = 0; nt < 16; ++nt) {
            __half2 h20 = __floats2half2_rn(__expf(c[nt][0] - mn0),
                                            __expf(c[nt][1] - mn0));
            __half2 h21 = __floats2half2_rn(__expf(c[nt][2] - mn1),
                                            __expf(c[nt][3] - mn1));
            p[nt][0] = *reinterpret_cast<uint32_t*>(&h20);
            p[nt][1] = *reinterpret_cast<uint32_t*>(&h21);
            float2 f0 = __half22float2(h20);
            float2 f1 = __half22float2(h21);
            lp0 += f0.x + f0.y;
            lp1 += f1.x + f1.y;
        }
        l0 = l0 * sc0 + lp0;
        l1 = l1 * sc1 + lp1;

        #pragma unroll
        for (int nt = 0; nt < 16; ++nt) {
            o[nt][0] *= sc0; o[nt][1] *= sc0;
            o[nt][2] *= sc1; o[nt][3] *= sc1;
        }

        // ---- O += P @ V (P C-frag reuses directly as A-frag) ----
        #pragma unroll
        for (int kk2 = 0; kk2 < 8; ++kk2) {
            const uint32_t a0 = p[2 * kk2][0];
            const uint32_t a1 = p[2 * kk2][1];
            const uint32_t a2 = p[2 * kk2 + 1][0];
            const uint32_t a3 = p[2 * kk2 + 1][1];
            #pragma unroll
            for (int nn2 = 0; nn2 < 8; ++nn2) {
                // V stored k-major [kv][f]; B frags via trans ldmatrix
                uint32_t va = stg + SV_OFF +
                    ((kk2 * 16 + (grp & 1) * 8 + lr) * VS
                     + (nn2 * 2 + (grp >> 1)) * 8) * 2;
                uint32_t v0, v1, v2, v3;
                ldsm4t(va, v0, v1, v2, v3);
                mma_f16(o[2 * nn2],     a0, a1, a2, a3, v0, v1);
                mma_f16(o[2 * nn2 + 1], a0, a1, a2, a3, v2, v3);
            }
        }
        __syncthreads();   // all warps done with this stage buffer
    }

    // Finalize: full-row l via quad shfl, normalize, store
    l0 += __shfl_xor_sync(0xffffffffu, l0, 1);
    l0 += __shfl_xor_sync(0xffffffffu, l0, 2);
    l1 += __shfl_xor_sync(0xffffffffu, l1, 1);
    l1 += __shfl_xor_sync(0xffffffffu, l1, 2);
    const float inv0 = 1.0f / l0;
    const float inv1 = 1.0f / l1;

    #pragma unroll
    for (int nt = 0; nt < 16; ++nt) {
        float2 w0 = make_float2(o[nt][0] * inv0, o[nt][1] * inv0);
        float2 w1 = make_float2(o[nt][2] * inv1, o[nt][3] * inv1);
        *reinterpret_cast<float2*>(&outb[(size_t)(wbase + g) * FDIM + nt * 8 + 2 * tig]) = w0;
        *reinterpret_cast<float2*>(&outb[(size_t)(wbase + g + 8) * FDIM + nt * 8 + 2 * tig]) = w1;
    }
}

// ---------------------------------------------------------------------------
// Fused projections (SIMT fp32), epilogues emit fp16 hi/lo splits.
// grid = (MROWS/64, 4): y=0 K(hi/lo), y=1 Q(hi/lo), y=2/3 V halves (fp16).
// ---------------------------------------------------------------------------
__global__ __launch_bounds__(256) void proj_fused_kernel(
    const float* __restrict__ x,
    const float* __restrict__ wk,
    const float* __restrict__ wq,
    const float* __restrict__ wv,
    __half* __restrict__ Kh, __half* __restrict__ Kl,
    __half* __restrict__ Qh, __half* __restrict__ Ql,
    __half* __restrict__ Vh) {
    __shared__ float sA[64][65];
    __shared__ float sB[64][65];

    const int which = blockIdx.y;
    const float* Bm;
    int Nout, colBase;
    if (which == 0)      { Bm = wk; Nout = 64;  colBase = 0;  }
    else if (which == 1) { Bm = wq; Nout = 64;  colBase = 0;  }
    else if (which == 2) { Bm = wv; Nout = 128; colBase = 0;  }
    else                 { Bm = wv; Nout = 128; colBase = 64; }

    const int tid = threadIdx.x;
    const int ty = tid >> 4;
    const int tx = tid & 15;
    const int r0 = ty * 4;
    const int c0 = tx * 4;
    const int blockRow = blockIdx.x * 64;

    float acc[4][4] = {};

    for (int kk = 0; kk < 128; kk += 64) {
        #pragma unroll
        for (int i = 0; i < 16; ++i) {
            int e = i * 256 + tid;
            int rr = e >> 6, cc = e & 63;
            sA[rr][cc] = x[(blockRow + rr) * 128 + kk + cc];
        }
        #pragma unroll
        for (int i = 0; i < 16; ++i) {
            int e = i * 256 + tid;
            int rr = e >> 6, cc = e & 63;
            sB[rr][cc] = Bm[(kk + rr) * Nout + colBase + cc];
        }
        __syncthreads();

        #pragma unroll 8
        for (int k = 0; k < 64; ++k) {
            float a[4], bb[4];
            #pragma unroll
            for (int i = 0; i < 4; ++i) a[i] = sA[r0 + i][k];
            #pragma unroll
            for (int j = 0; j < 4; ++j) bb[j] = sB[k][c0 + j];
            #pragma unroll
            for (int i = 0; i < 4; ++i)
                #pragma unroll
                for (int j = 0; j < 4; ++j)
                    acc[i][j] = fmaf(a[i], bb[j], acc[i][j]);
        }
        __syncthreads();
    }

    if (which < 2) {
        __half* Hh = (which == 0) ? Kh : Qh;
        __half* Hl = (which == 0) ? Kl : Ql;
        #pragma unroll
        for (int i = 0; i < 4; ++i)
            #pragma unroll
            for (int j = 0; j < 4; ++j) {
                const size_t idx = (size_t)(blockRow + r0 + i) * 64 + c0 + j;
                const float a = acc[i][j];
                const __half hi = __float2half_rn(a);
                Hh[idx] = hi;
                Hl[idx] = __float2half_rn(a - __half2float(hi));
            }
    } else {
        #pragma unroll
        for (int i = 0; i < 4; ++i)
            #pragma unroll
            for (int j = 0; j < 4; ++j)
                Vh[(size_t)(blockRow + r0 + i) * 128 + colBase + c0 + j] =
                    __float2half_rn(acc[i][j]);
    }
}

// ---------------------------------------------------------------------------
extern "C" void kernel_launch(void* const* d_in, const int* in_sizes, int n_in,
                              void* d_out, int out_size) {
    const float* x  = (const float*)d_in[0];
    // d_in[1] = adj (bool), unused by the reference math
    const float* wk = (const float*)d_in[2];
    const float* wv = (const float*)d_in[3];
    const float* wq = (const float*)d_in[4];
    float* out = (float*)d_out;

    void *pQh, *pQl, *pKh, *pKl, *pVh;
    cudaGetSymbolAddress(&pQh, g_Qh);
    cudaGetSymbolAddress(&pQl, g_Ql);
    cudaGetSymbolAddress(&pKh, g_Kh);
    cudaGetSymbolAddress(&pKl, g_Kl);
    cudaGetSymbolAddress(&pVh, g_Vh);

    cudaFuncSetAttribute(attn_mma_kernel,
                         cudaFuncAttributeMaxDynamicSharedMemorySize, ATTN_SMEM);

    proj_fused_kernel<<<dim3(MROWS / 64, 4), 256>>>(
        x, wk, wq, wv,
        (__half*)pKh, (__half*)pKl, (__half*)pQh, (__half*)pQl, (__half*)pVh);

    attn_mma_kernel<<<dim3(SEQ / 128, BATCH), 256, ATTN_SMEM>>>(
        (const __half*)pQh, (const __half*)pQl,
        (const __half*)pKh, (const __half*)pKl,
        (const __half*)pVh, out);
}

// round 8
// speedup vs baseline: 6.2617x; 1.2256x over previous
#include <cuda_runtime.h>
#include <cuda_fp16.h>
#include <cstdint>
#include <math.h>

// Problem constants
#define BATCH 8
#define SEQ   2048
#define FDIM  128
#define WDIM  64
#define MROWS (BATCH * SEQ)   // 16384

#define LOG2E 1.44269504088896f

// Scratch (device globals: allocation-free rule)
// Qh/Ql hold Q * log2(e) split hi/lo (softmax uses ex2 directly).
__device__ __half g_Qh[MROWS * WDIM];
__device__ __half g_Ql[MROWS * WDIM];
__device__ __half g_Kh[MROWS * WDIM];
__device__ __half g_Kl[MROWS * WDIM];
__device__ __half g_Vh[MROWS * FDIM];

// ---------------------------------------------------------------------------
// PTX helpers (baseline ISA: ldmatrix sm_75+, mma sm_80+, cp.async sm_80+)
// ---------------------------------------------------------------------------
__device__ __forceinline__ uint32_t cvta_s(const void* p) {
    uint32_t a;
    asm("{ .reg .u64 t; cvta.to.shared.u64 t, %1; cvt.u32.u64 %0, t; }"
        : "=r"(a) : "l"(p));
    return a;
}
__device__ __forceinline__ void ldsm4(uint32_t addr, uint32_t& r0, uint32_t& r1,
                                      uint32_t& r2, uint32_t& r3) {
    asm volatile("ldmatrix.sync.aligned.m8n8.x4.shared.b16 {%0,%1,%2,%3}, [%4];"
                 : "=r"(r0), "=r"(r1), "=r"(r2), "=r"(r3) : "r"(addr));
}
__device__ __forceinline__ void ldsm4t(uint32_t addr, uint32_t& r0, uint32_t& r1,
                                       uint32_t& r2, uint32_t& r3) {
    asm volatile("ldmatrix.sync.aligned.m8n8.x4.trans.shared.b16 {%0,%1,%2,%3}, [%4];"
                 : "=r"(r0), "=r"(r1), "=r"(r2), "=r"(r3) : "r"(addr));
}
__device__ __forceinline__ void mma_f16(float* c, uint32_t a0, uint32_t a1,
                                        uint32_t a2, uint32_t a3,
                                        uint32_t b0, uint32_t b1) {
    asm volatile(
        "mma.sync.aligned.m16n8k16.row.col.f32.f16.f16.f32 "
        "{%0,%1,%2,%3}, {%4,%5,%6,%7}, {%8,%9}, {%0,%1,%2,%3};"
        : "+f"(c[0]), "+f"(c[1]), "+f"(c[2]), "+f"(c[3])
        : "r"(a0), "r"(a1), "r"(a2), "r"(a3), "r"(b0), "r"(b1));
}
__device__ __forceinline__ void cpa16(uint32_t d, const void* s) {
    asm volatile("cp.async.cg.shared.global [%0], [%1], 16;" :: "r"(d), "l"(s));
}
#define CP_COMMIT() asm volatile("cp.async.commit_group;" ::: "memory")
#define CP_WAIT1()  asm volatile("cp.async.wait_group 1;" ::: "memory")
#define CP_WAIT0()  asm volatile("cp.async.wait_group 0;" ::: "memory")

__device__ __forceinline__ float ex2(float x) {
    float y;
    asm("ex2.approx.ftz.f32 %0, %1;" : "=f"(y) : "f"(x));
    return y;
}

// ---------------------------------------------------------------------------
// Attention SMEM layout (bytes). Padded strides keep ldmatrix conflict-free.
// ---------------------------------------------------------------------------
#define QS 72
#define KS 72
#define VS 136
#define SQH_OFF  0
#define SQL_OFF  (128 * QS * 2)             // 18432
#define STAGE_OFF (2 * 128 * QS * 2)        // 36864
#define KH_OFF   0
#define KL_OFF   (128 * KS * 2)             // 18432
#define SV_OFF   (2 * 128 * KS * 2)         // 36864
#define STAGE_SZ (2 * 128 * KS * 2 + 128 * VS * 2)   // 71680
#define ATTN_SMEM (STAGE_OFF + 2 * STAGE_SZ)         // 180224

__device__ __forceinline__ void stage_load(uint32_t base,
                                           const __half* Khb, const __half* Klb,
                                           const __half* Vhb, int kv0, int tid) {
    #pragma unroll
    for (int i = 0; i < 4; ++i) {
        int c = i * 256 + tid;
        int r = c >> 3, c8 = (c & 7) * 8;
        cpa16(base + KH_OFF + (r * KS + c8) * 2, Khb + (size_t)(kv0 + r) * WDIM + c8);
        cpa16(base + KL_OFF + (r * KS + c8) * 2, Klb + (size_t)(kv0 + r) * WDIM + c8);
    }
    #pragma unroll
    for (int i = 0; i < 8; ++i) {
        int c = i * 256 + tid;
        int r = c >> 4, c8 = (c & 15) * 8;
        cpa16(base + SV_OFF + (r * VS + c8) * 2, Vhb + (size_t)(kv0 + r) * FDIM + c8);
    }
}

// ---------------------------------------------------------------------------
// FA2-style fused attention on mma.sync fp16.
// grid = (SEQ/128, BATCH) = (16, 8), 256 threads (8 warps x 16 q-rows).
// Q is pre-scaled by log2(e): softmax uses raw ex2.
// ---------------------------------------------------------------------------
__global__ __launch_bounds__(256, 1) void attn_mma_kernel(
    const __half* __restrict__ Qh, const __half* __restrict__ Ql,
    const __half* __restrict__ Kh, const __half* __restrict__ Kl,
    const __half* __restrict__ Vh, float* __restrict__ out) {
    extern __shared__ char smem[];
    const uint32_t sb = cvta_s(smem);
    const int tid = threadIdx.x;
    const int wid = tid >> 5;
    const int lane = tid & 31;
    const int g = lane >> 2;
    const int tig = lane & 3;
    const int grp = lane >> 3;
    const int lr = lane & 7;
    const int wbase = wid * 16;

    const int b = blockIdx.y;
    const int q0 = blockIdx.x * 128;
    const __half* Qhb = Qh + ((size_t)b * SEQ + q0) * WDIM;
    const __half* Qlb = Ql + ((size_t)b * SEQ + q0) * WDIM;
    const __half* Khb = Kh + (size_t)b * SEQ * WDIM;
    const __half* Klb = Kl + (size_t)b * SEQ * WDIM;
    const __half* Vhb = Vh + (size_t)b * SEQ * FDIM;
    float* outb = out + ((size_t)b * SEQ + q0) * FDIM;

    #pragma unroll
    for (int i = 0; i < 4; ++i) {
        int c = i * 256 + tid;
        int r = c >> 3, c8 = (c & 7) * 8;
        cpa16(sb + SQH_OFF + (r * QS + c8) * 2, Qhb + (size_t)r * WDIM + c8);
        cpa16(sb + SQL_OFF + (r * QS + c8) * 2, Qlb + (size_t)r * WDIM + c8);
    }
    CP_COMMIT();
    stage_load(sb + STAGE_OFF, Khb, Klb, Vhb, 0, tid);
    CP_COMMIT();

    CP_WAIT1();
    __syncthreads();
    uint32_t qh[4][4], ql[4][4];
    #pragma unroll
    for (int kk = 0; kk < 4; ++kk) {
        uint32_t a = sb + SQH_OFF +
            ((wbase + lr + (grp & 1) * 8) * QS + kk * 16 + (grp >> 1) * 8) * 2;
        ldsm4(a, qh[kk][0], qh[kk][1], qh[kk][2], qh[kk][3]);
        uint32_t al = a + (SQL_OFF - SQH_OFF);
        ldsm4(al, ql[kk][0], ql[kk][1], ql[kk][2], ql[kk][3]);
    }

    float o[16][4];
    #pragma unroll
    for (int nt = 0; nt < 16; ++nt)
        #pragma unroll
        for (int j = 0; j < 4; ++j) o[nt][j] = 0.0f;
    float m0 = -INFINITY, m1 = -INFINITY, l0 = 0.0f, l1 = 0.0f;

    for (int t = 0; t < 16; ++t) {
        if (t + 1 < 16) {
            stage_load(sb + STAGE_OFF + ((t + 1) & 1) * STAGE_SZ,
                       Khb, Klb, Vhb, (t + 1) * 128, tid);
            CP_COMMIT();
            CP_WAIT1();
        } else {
            CP_WAIT0();
        }
        __syncthreads();

        const uint32_t stg = sb + STAGE_OFF + (t & 1) * STAGE_SZ;

        // ---- S' = (Q*log2e) K^T (3 fp16 MMAs: hi*hi + hi*lo + lo*hi) ----
        float c[16][4];
        #pragma unroll
        for (int nt = 0; nt < 16; ++nt)
            #pragma unroll
            for (int j = 0; j < 4; ++j) c[nt][j] = 0.0f;

        #pragma unroll
        for (int kk = 0; kk < 4; ++kk) {
            #pragma unroll
            for (int nn2 = 0; nn2 < 8; ++nn2) {
                uint32_t off = (((nn2 * 2 + (grp >> 1)) * 8 + lr) * KS
                                + kk * 16 + (grp & 1) * 8) * 2;
                uint32_t h0, h1, h2, h3, e0, e1, e2, e3;
                ldsm4(stg + KH_OFF + off, h0, h1, h2, h3);
                ldsm4(stg + KL_OFF + off, e0, e1, e2, e3);
                mma_f16(c[2 * nn2],     qh[kk][0], qh[kk][1], qh[kk][2], qh[kk][3], h0, h1);
                mma_f16(c[2 * nn2 + 1], qh[kk][0], qh[kk][1], qh[kk][2], qh[kk][3], h2, h3);
                mma_f16(c[2 * nn2],     qh[kk][0], qh[kk][1], qh[kk][2], qh[kk][3], e0, e1);
                mma_f16(c[2 * nn2 + 1], qh[kk][0], qh[kk][1], qh[kk][2], qh[kk][3], e2, e3);
                mma_f16(c[2 * nn2],     ql[kk][0], ql[kk][1], ql[kk][2], ql[kk][3], h0, h1);
                mma_f16(c[2 * nn2 + 1], ql[kk][0], ql[kk][1], ql[kk][2], ql[kk][3], h2, h3);
            }
        }

        // ---- Online softmax in registers (base-2) ----
        float mt0 = -INFINITY, mt1 = -INFINITY;
        #pragma unroll
        for (int nt = 0; nt < 16; ++nt) {
            mt0 = fmaxf(mt0, fmaxf(c[nt][0], c[nt][1]));
            mt1 = fmaxf(mt1, fmaxf(c[nt][2], c[nt][3]));
        }
        mt0 = fmaxf(mt0, __shfl_xor_sync(0xffffffffu, mt0, 1));
        mt0 = fmaxf(mt0, __shfl_xor_sync(0xffffffffu, mt0, 2));
        mt1 = fmaxf(mt1, __shfl_xor_sync(0xffffffffu, mt1, 1));
        mt1 = fmaxf(mt1, __shfl_xor_sync(0xffffffffu, mt1, 2));

        const float mn0 = fmaxf(m0, mt0);
        const float mn1 = fmaxf(m1, mt1);
        const float sc0 = ex2(m0 - mn0);   // first tile: ex2(-inf) = 0
        const float sc1 = ex2(m1 - mn1);
        m0 = mn0; m1 = mn1;

        uint32_t p[16][2];
        float lp0 = 0.0f, lp1 = 0.0f;
        #pragma unroll
        for (int nt = 0; nt < 16; ++nt) {
            const float e00 = ex2(c[nt][0] - mn0);
            const float e01 = ex2(c[nt][1] - mn0);
            const float e10 = ex2(c[nt][2] - mn1);
            const float e11 = ex2(c[nt][3] - mn1);
            lp0 += e00 + e01;
            lp1 += e10 + e11;
            __half2 h20 = __floats2half2_rn(e00, e01);
            __half2 h21 = __floats2half2_rn(e10, e11);
            p[nt][0] = *reinterpret_cast<uint32_t*>(&h20);
            p[nt][1] = *reinterpret_cast<uint32_t*>(&h21);
        }
        l0 = l0 * sc0 + lp0;
        l1 = l1 * sc1 + lp1;

        #pragma unroll
        for (int nt = 0; nt < 16; ++nt) {
            o[nt][0] *= sc0; o[nt][1] *= sc0;
            o[nt][2] *= sc1; o[nt][3] *= sc1;
        }

        // ---- O += P @ V ----
        #pragma unroll
        for (int kk2 = 0; kk2 < 8; ++kk2) {
            const uint32_t a0 = p[2 * kk2][0];
            const uint32_t a1 = p[2 * kk2][1];
            const uint32_t a2 = p[2 * kk2 + 1][0];
            const uint32_t a3 = p[2 * kk2 + 1][1];
            #pragma unroll
            for (int nn2 = 0; nn2 < 8; ++nn2) {
                uint32_t va = stg + SV_OFF +
                    ((kk2 * 16 + (grp & 1) * 8 + lr) * VS
                     + (nn2 * 2 + (grp >> 1)) * 8) * 2;
                uint32_t v0, v1, v2, v3;
                ldsm4t(va, v0, v1, v2, v3);
                mma_f16(o[2 * nn2],     a0, a1, a2, a3, v0, v1);
                mma_f16(o[2 * nn2 + 1], a0, a1, a2, a3, v2, v3);
            }
        }
        __syncthreads();
    }

    l0 += __shfl_xor_sync(0xffffffffu, l0, 1);
    l0 += __shfl_xor_sync(0xffffffffu, l0, 2);
    l1 += __shfl_xor_sync(0xffffffffu, l1, 1);
    l1 += __shfl_xor_sync(0xffffffffu, l1, 2);
    const float inv0 = 1.0f / l0;
    const float inv1 = 1.0f / l1;

    #pragma unroll
    for (int nt = 0; nt < 16; ++nt) {
        float2 w0 = make_float2(o[nt][0] * inv0, o[nt][1] * inv0);
        float2 w1 = make_float2(o[nt][2] * inv1, o[nt][3] * inv1);
        *reinterpret_cast<float2*>(&outb[(size_t)(wbase + g) * FDIM + nt * 8 + 2 * tig]) = w0;
        *reinterpret_cast<float2*>(&outb[(size_t)(wbase + g + 8) * FDIM + nt * 8 + 2 * tig]) = w1;
    }
}

// ---------------------------------------------------------------------------
// Tensor-core projections. grid = (MROWS/128, 3): y=0 K, y=1 Q (scaled by
// log2e, hi/lo outputs), y=2 V (fp16 output, 2-term product).
// x is split hi/lo in-kernel (L2-resident across the 3 y-slices); w is
// transposed + split in smem. Q,K use 3-term compensated fp16 product.
// ---------------------------------------------------------------------------
#define PXS 136                                  // half stride (272 B rows)
#define PXH_OFF 0
#define PXL_OFF (128 * PXS * 2)                  // 34816
#define PWH_OFF (2 * 128 * PXS * 2)              // 69632
#define PWL_OFF (PWH_OFF + 128 * PXS * 2)        // 104448
#define PROJ_SMEM (PWL_OFF + 128 * PXS * 2)      // 139264

__global__ __launch_bounds__(256, 1) void proj_mma_kernel(
    const float* __restrict__ x,
    const float* __restrict__ wk,
    const float* __restrict__ wq,
    const float* __restrict__ wv,
    __half* __restrict__ Kh, __half* __restrict__ Kl,
    __half* __restrict__ Qh, __half* __restrict__ Ql,
    __half* __restrict__ Vh) {
    extern __shared__ char ps[];
    const uint32_t sb = cvta_s(ps);
    const int tid = threadIdx.x;
    const int wid = tid >> 5;
    const int lane = tid & 31;
    const int g = lane >> 2;
    const int tig = lane & 3;
    const int grp = lane >> 3;
    const int lr = lane & 7;
    const int wbase = wid * 16;

    const int which = blockIdx.y;
    const int row0 = blockIdx.x * 128;
    const float* w = (which == 0) ? wk : (which == 1) ? wq : wv;
    const int Nout = (which == 2) ? 128 : 64;

    // Load + split x tile [128][128] fp32 -> hi/lo fp16 (smem)
    #pragma unroll
    for (int i = 0; i < 16; ++i) {
        int e = i * 256 + tid;
        int r = e >> 5;
        int c4 = (e & 31) * 4;
        float4 v = *reinterpret_cast<const float4*>(&x[(size_t)(row0 + r) * 128 + c4]);
        __half hx = __float2half_rn(v.x), hy = __float2half_rn(v.y);
        __half hz = __float2half_rn(v.z), hw = __float2half_rn(v.w);
        char* dh = ps + PXH_OFF + ((size_t)r * PXS + c4) * 2;
        char* dl = ps + PXL_OFF + ((size_t)r * PXS + c4) * 2;
        *reinterpret_cast<__half2*>(dh)     = __halves2half2(hx, hy);
        *reinterpret_cast<__half2*>(dh + 4) = __halves2half2(hz, hw);
        *reinterpret_cast<__half2*>(dl) = __halves2half2(
            __float2half_rn(v.x - __half2float(hx)),
            __float2half_rn(v.y - __half2float(hy)));
        *reinterpret_cast<__half2*>(dl + 4) = __halves2half2(
            __float2half_rn(v.z - __half2float(hz)),
            __float2half_rn(v.w - __half2float(hw)));
    }
    // Load + transpose + split w [128][Nout] -> wT[n][k] hi/lo (smem)
    for (int e = tid; e < 128 * Nout; e += 256) {
        int k = (Nout == 64) ? (e >> 6) : (e >> 7);
        int n = e & (Nout - 1);
        float v = w[(size_t)k * Nout + n];
        __half hi = __float2half_rn(v);
        *reinterpret_cast<__half*>(ps + PWH_OFF + ((size_t)n * PXS + k) * 2) = hi;
        *reinterpret_cast<__half*>(ps + PWL_OFF + ((size_t)n * PXS + k) * 2) =
            __float2half_rn(v - __half2float(hi));
    }
    __syncthreads();

    // A-frags (x hi/lo), 8 k-steps
    uint32_t ah[8][4], al[8][4];
    #pragma unroll
    for (int kk = 0; kk < 8; ++kk) {
        uint32_t a = sb + PXH_OFF +
            ((wbase + lr + (grp & 1) * 8) * PXS + kk * 16 + (grp >> 1) * 8) * 2;
        ldsm4(a, ah[kk][0], ah[kk][1], ah[kk][2], ah[kk][3]);
        ldsm4(a + (PXL_OFF - PXH_OFF), al[kk][0], al[kk][1], al[kk][2], al[kk][3]);
    }

    if (which < 2) {
        // K or Q: N=64, 3-term compensated product
        float c[8][4];
        #pragma unroll
        for (int nt = 0; nt < 8; ++nt)
            #pragma unroll
            for (int j = 0; j < 4; ++j) c[nt][j] = 0.0f;

        #pragma unroll
        for (int kk = 0; kk < 8; ++kk) {
            #pragma unroll
            for (int nn2 = 0; nn2 < 4; ++nn2) {
                uint32_t off = (((nn2 * 2 + (grp >> 1)) * 8 + lr) * PXS
                                + kk * 16 + (grp & 1) * 8) * 2;
                uint32_t h0, h1, h2, h3, e0, e1, e2, e3;
                ldsm4(sb + PWH_OFF + off, h0, h1, h2, h3);
                ldsm4(sb + PWL_OFF + off, e0, e1, e2, e3);
                mma_f16(c[2 * nn2],     ah[kk][0], ah[kk][1], ah[kk][2], ah[kk][3], h0, h1);
                mma_f16(c[2 * nn2 + 1], ah[kk][0], ah[kk][1], ah[kk][2], ah[kk][3], h2, h3);
                mma_f16(c[2 * nn2],     ah[kk][0], ah[kk][1], ah[kk][2], ah[kk][3], e0, e1);
                mma_f16(c[2 * nn2 + 1], ah[kk][0], ah[kk][1], ah[kk][2], ah[kk][3], e2, e3);
                mma_f16(c[2 * nn2],     al[kk][0], al[kk][1], al[kk][2], al[kk][3], h0, h1);
                mma_f16(c[2 * nn2 + 1], al[kk][0], al[kk][1], al[kk][2], al[kk][3], h2, h3);
            }
        }

        const float scale = (which == 1) ? LOG2E : 1.0f;  // fold log2e into Q
        __half* Hh = (which == 0) ? Kh : Qh;
        __half* Hl = (which == 0) ? Kl : Ql;
        #pragma unroll
        for (int nt = 0; nt < 8; ++nt) {
            const int col = nt * 8 + 2 * tig;
            #pragma unroll
            for (int half_m = 0; half_m < 2; ++half_m) {
                const size_t idx =
                    (size_t)(row0 + wbase + g + half_m * 8) * WDIM + col;
                const float v0 = c[nt][2 * half_m] * scale;
                const float v1 = c[nt][2 * half_m + 1] * scale;
                const __half h0 = __float2half_rn(v0);
                const __half h1 = __float2half_rn(v1);
                *reinterpret_cast<__half2*>(&Hh[idx]) = __halves2half2(h0, h1);
                *reinterpret_cast<__half2*>(&Hl[idx]) = __halves2half2(
                    __float2half_rn(v0 - __half2float(h0)),
                    __float2half_rn(v1 - __half2float(h1)));
            }
        }
    } else {
        // V: N=128, 2-term (full x, w hi only) — fp16 output absorbs the error
        float c[16][4];
        #pragma unroll
        for (int nt = 0; nt < 16; ++nt)
            #pragma unroll
            for (int j = 0; j < 4; ++j) c[nt][j] = 0.0f;

        #pragma unroll
        for (int kk = 0; kk < 8; ++kk) {
            #pragma unroll
            for (int nn2 = 0; nn2 < 8; ++nn2) {
                uint32_t off = (((nn2 * 2 + (grp >> 1)) * 8 + lr) * PXS
                                + kk * 16 + (grp & 1) * 8) * 2;
                uint32_t h0, h1, h2, h3;
                ldsm4(sb + PWH_OFF + off, h0, h1, h2, h3);
                mma_f16(c[2 * nn2],     ah[kk][0], ah[kk][1], ah[kk][2], ah[kk][3], h0, h1);
                mma_f16(c[2 * nn2 + 1], ah[kk][0], ah[kk][1], ah[kk][2], ah[kk][3], h2, h3);
                mma_f16(c[2 * nn2],     al[kk][0], al[kk][1], al[kk][2], al[kk][3], h0, h1);
                mma_f16(c[2 * nn2 + 1], al[kk][0], al[kk][1], al[kk][2], al[kk][3], h2, h3);
            }
        }

        #pragma unroll
        for (int nt = 0; nt < 16; ++nt) {
            const int col = nt * 8 + 2 * tig;
            #pragma unroll
            for (int half_m = 0; half_m < 2; ++half_m) {
                const size_t idx =
                    (size_t)(row0 + wbase + g + half_m * 8) * FDIM + col;
                *reinterpret_cast<__half2*>(&Vh[idx]) = __halves2half2(
                    __float2half_rn(c[nt][2 * half_m]),
                    __float2half_rn(c[nt][2 * half_m + 1]));
            }
        }
    }
}

// ---------------------------------------------------------------------------
extern "C" void kernel_launch(void* const* d_in, const int* in_sizes, int n_in,
                              void* d_out, int out_size) {
    const float* x  = (const float*)d_in[0];
    // d_in[1] = adj (bool), unused by the reference math
    const float* wk = (const float*)d_in[2];
    const float* wv = (const float*)d_in[3];
    const float* wq = (const float*)d_in[4];
    float* out = (float*)d_out;

    void *pQh, *pQl, *pKh, *pKl, *pVh;
    cudaGetSymbolAddress(&pQh, g_Qh);
    cudaGetSymbolAddress(&pQl, g_Ql);
    cudaGetSymbolAddress(&pKh, g_Kh);
    cudaGetSymbolAddress(&pKl, g_Kl);
    cudaGetSymbolAddress(&pVh, g_Vh);

    cudaFuncSetAttribute(attn_mma_kernel,
                         cudaFuncAttributeMaxDynamicSharedMemorySize, ATTN_SMEM);
    cudaFuncSetAttribute(proj_mma_kernel,
                         cudaFuncAttributeMaxDynamicSharedMemorySize, PROJ_SMEM);

    proj_mma_kernel<<<dim3(MROWS / 128, 3), 256, PROJ_SMEM>>>(
        x, wk, wq, wv,
        (__half*)pKh, (__half*)pKl, (__half*)pQh, (__half*)pQl, (__half*)pVh);

    attn_mma_kernel<<<dim3(SEQ / 128, BATCH), 256, ATTN_SMEM>>>(
        (const __half*)pQh, (const __half*)pQl,
        (const __half*)pKh, (const __half*)pKl,
        (const __half*)pVh, out);
}

// round 9
// speedup vs baseline: 6.7196x; 1.0731x over previous
#include <cuda_runtime.h>
#include <cuda_fp16.h>
#include <cstdint>
#include <math.h>

// Problem constants
#define BATCH 8
#define SEQ   2048
#define FDIM  128
#define WDIM  64
#define MROWS (BATCH * SEQ)   // 16384

#define LOG2E 1.44269504088896f

// Scratch (device globals: allocation-free rule)
// Qh/Ql hold Q * log2(e) split hi/lo (softmax uses ex2 directly).
__device__ __half g_Qh[MROWS * WDIM];
__device__ __half g_Ql[MROWS * WDIM];
__device__ __half g_Kh[MROWS * WDIM];
__device__ __half g_Kl[MROWS * WDIM];
__device__ __half g_Vh[MROWS * FDIM];

// ---------------------------------------------------------------------------
// PTX helpers (baseline ISA: ldmatrix sm_75+, mma sm_80+, cp.async sm_80+)
// ---------------------------------------------------------------------------
__device__ __forceinline__ uint32_t cvta_s(const void* p) {
    uint32_t a;
    asm("{ .reg .u64 t; cvta.to.shared.u64 t, %1; cvt.u32.u64 %0, t; }"
        : "=r"(a) : "l"(p));
    return a;
}
__device__ __forceinline__ void ldsm4(uint32_t addr, uint32_t& r0, uint32_t& r1,
                                      uint32_t& r2, uint32_t& r3) {
    asm volatile("ldmatrix.sync.aligned.m8n8.x4.shared.b16 {%0,%1,%2,%3}, [%4];"
                 : "=r"(r0), "=r"(r1), "=r"(r2), "=r"(r3) : "r"(addr));
}
__device__ __forceinline__ void ldsm4t(uint32_t addr, uint32_t& r0, uint32_t& r1,
                                       uint32_t& r2, uint32_t& r3) {
    asm volatile("ldmatrix.sync.aligned.m8n8.x4.trans.shared.b16 {%0,%1,%2,%3}, [%4];"
                 : "=r"(r0), "=r"(r1), "=r"(r2), "=r"(r3) : "r"(addr));
}
__device__ __forceinline__ void mma_f16(float* c, uint32_t a0, uint32_t a1,
                                        uint32_t a2, uint32_t a3,
                                        uint32_t b0, uint32_t b1) {
    asm volatile(
        "mma.sync.aligned.m16n8k16.row.col.f32.f16.f16.f32 "
        "{%0,%1,%2,%3}, {%4,%5,%6,%7}, {%8,%9}, {%0,%1,%2,%3};"
        : "+f"(c[0]), "+f"(c[1]), "+f"(c[2]), "+f"(c[3])
        : "r"(a0), "r"(a1), "r"(a2), "r"(a3), "r"(b0), "r"(b1));
}
__device__ __forceinline__ void cpa16(uint32_t d, const void* s) {
    asm volatile("cp.async.cg.shared.global [%0], [%1], 16;" :: "r"(d), "l"(s));
}
#define CP_COMMIT() asm volatile("cp.async.commit_group;" ::: "memory")
#define CP_WAIT1()  asm volatile("cp.async.wait_group 1;" ::: "memory")
#define CP_WAIT0()  asm volatile("cp.async.wait_group 0;" ::: "memory")

__device__ __forceinline__ float ex2(float x) {
    float y;
    asm("ex2.approx.ftz.f32 %0, %1;" : "=f"(y) : "f"(x));
    return y;
}

// ---------------------------------------------------------------------------
// Attention SMEM layout (bytes). Padded strides keep ldmatrix conflict-free.
// ---------------------------------------------------------------------------
#define QS 72
#define KS 72
#define VS 136
#define SQH_OFF  0
#define SQL_OFF  (128 * QS * 2)             // 18432
#define STAGE_OFF (2 * 128 * QS * 2)        // 36864
#define KH_OFF   0
#define KL_OFF   (128 * KS * 2)             // 18432
#define SV_OFF   (2 * 128 * KS * 2)         // 36864
#define STAGE_SZ (2 * 128 * KS * 2 + 128 * VS * 2)   // 71680
#define ATTN_SMEM (STAGE_OFF + 2 * STAGE_SZ)         // 180224

__device__ __forceinline__ void stage_load(uint32_t base,
                                           const __half* Khb, const __half* Klb,
                                           const __half* Vhb, int kv0, int tid) {
    #pragma unroll
    for (int i = 0; i < 4; ++i) {
        int c = i * 256 + tid;
        int r = c >> 3, c8 = (c & 7) * 8;
        cpa16(base + KH_OFF + (r * KS + c8) * 2, Khb + (size_t)(kv0 + r) * WDIM + c8);
        cpa16(base + KL_OFF + (r * KS + c8) * 2, Klb + (size_t)(kv0 + r) * WDIM + c8);
    }
    #pragma unroll
    for (int i = 0; i < 8; ++i) {
        int c = i * 256 + tid;
        int r = c >> 4, c8 = (c & 15) * 8;
        cpa16(base + SV_OFF + (r * VS + c8) * 2, Vhb + (size_t)(kv0 + r) * FDIM + c8);
    }
}

// ---------------------------------------------------------------------------
// FA2-style fused attention on mma.sync fp16, with the 128-kv tile split into
// two 64-col halves software-pipelined so softmax(A) overlaps QK(B) drain and
// softmax(B) overlaps PV(A) drain in the tensor pipe.
// grid = (SEQ/128, BATCH) = (16, 8), 256 threads (8 warps x 16 q-rows).
// Q is pre-scaled by log2(e): softmax uses raw ex2.
// ---------------------------------------------------------------------------
__global__ __launch_bounds__(256, 1) void attn_mma_kernel(
    const __half* __restrict__ Qh, const __half* __restrict__ Ql,
    const __half* __restrict__ Kh, const __half* __restrict__ Kl,
    const __half* __restrict__ Vh, float* __restrict__ out) {
    extern __shared__ char smem[];
    const uint32_t sb = cvta_s(smem);
    const int tid = threadIdx.x;
    const int lane = tid & 31;
    const int g = lane >> 2;
    const int tig = lane & 3;
    const int grp = lane >> 3;
    const int lr = lane & 7;
    const int wbase = (tid >> 5) * 16;

    const int b = blockIdx.y;
    const int q0 = blockIdx.x * 128;
    const __half* Qhb = Qh + ((size_t)b * SEQ + q0) * WDIM;
    const __half* Qlb = Ql + ((size_t)b * SEQ + q0) * WDIM;
    const __half* Khb = Kh + (size_t)b * SEQ * WDIM;
    const __half* Klb = Kl + (size_t)b * SEQ * WDIM;
    const __half* Vhb = Vh + (size_t)b * SEQ * FDIM;
    float* outb = out + ((size_t)b * SEQ + q0) * FDIM;

    #pragma unroll
    for (int i = 0; i < 4; ++i) {
        int c = i * 256 + tid;
        int r = c >> 3, c8 = (c & 7) * 8;
        cpa16(sb + SQH_OFF + (r * QS + c8) * 2, Qhb + (size_t)r * WDIM + c8);
        cpa16(sb + SQL_OFF + (r * QS + c8) * 2, Qlb + (size_t)r * WDIM + c8);
    }
    CP_COMMIT();
    stage_load(sb + STAGE_OFF, Khb, Klb, Vhb, 0, tid);
    CP_COMMIT();

    CP_WAIT1();
    __syncthreads();
    uint32_t qh[4][4], ql[4][4];
    #pragma unroll
    for (int kk = 0; kk < 4; ++kk) {
        uint32_t a = sb + SQH_OFF +
            ((wbase + lr + (grp & 1) * 8) * QS + kk * 16 + (grp >> 1) * 8) * 2;
        ldsm4(a, qh[kk][0], qh[kk][1], qh[kk][2], qh[kk][3]);
        uint32_t al = a + (SQL_OFF - SQH_OFF);
        ldsm4(al, ql[kk][0], ql[kk][1], ql[kk][2], ql[kk][3]);
    }

    float o[16][4];
    #pragma unroll
    for (int nt = 0; nt < 16; ++nt)
        #pragma unroll
        for (int j = 0; j < 4; ++j) o[nt][j] = 0.0f;
    float m0 = -INFINITY, m1 = -INFINITY, l0 = 0.0f, l1 = 0.0f;

    for (int t = 0; t < 16; ++t) {
        if (t + 1 < 16) {
            stage_load(sb + STAGE_OFF + ((t + 1) & 1) * STAGE_SZ,
                       Khb, Klb, Vhb, (t + 1) * 128, tid);
            CP_COMMIT();
            CP_WAIT1();
        } else {
            CP_WAIT0();
        }
        __syncthreads();

        const uint32_t stg = sb + STAGE_OFF + (t & 1) * STAGE_SZ;

        // ---- QK half A (kv cols 0..63) and half B (64..127), issued
        //      back-to-back so B drains under softmax(A) ----
        float ca[8][4], cb[8][4];
        #pragma unroll
        for (int nt = 0; nt < 8; ++nt)
            #pragma unroll
            for (int j = 0; j < 4; ++j) { ca[nt][j] = 0.0f; cb[nt][j] = 0.0f; }

        #pragma unroll
        for (int kk = 0; kk < 4; ++kk) {
            #pragma unroll
            for (int nn2 = 0; nn2 < 4; ++nn2) {
                uint32_t off = (((nn2 * 2 + (grp >> 1)) * 8 + lr) * KS
                                + kk * 16 + (grp & 1) * 8) * 2;
                uint32_t h0, h1, h2, h3, e0, e1, e2, e3;
                ldsm4(stg + KH_OFF + off, h0, h1, h2, h3);
                ldsm4(stg + KL_OFF + off, e0, e1, e2, e3);
                mma_f16(ca[2 * nn2],     qh[kk][0], qh[kk][1], qh[kk][2], qh[kk][3], h0, h1);
                mma_f16(ca[2 * nn2 + 1], qh[kk][0], qh[kk][1], qh[kk][2], qh[kk][3], h2, h3);
                mma_f16(ca[2 * nn2],     qh[kk][0], qh[kk][1], qh[kk][2], qh[kk][3], e0, e1);
                mma_f16(ca[2 * nn2 + 1], qh[kk][0], qh[kk][1], qh[kk][2], qh[kk][3], e2, e3);
                mma_f16(ca[2 * nn2],     ql[kk][0], ql[kk][1], ql[kk][2], ql[kk][3], h0, h1);
                mma_f16(ca[2 * nn2 + 1], ql[kk][0], ql[kk][1], ql[kk][2], ql[kk][3], h2, h3);
            }
        }
        #pragma unroll
        for (int kk = 0; kk < 4; ++kk) {
            #pragma unroll
            for (int nn2 = 4; nn2 < 8; ++nn2) {
                const int nb = nn2 - 4;
                uint32_t off = (((nn2 * 2 + (grp >> 1)) * 8 + lr) * KS
                                + kk * 16 + (grp & 1) * 8) * 2;
                uint32_t h0, h1, h2, h3, e0, e1, e2, e3;
                ldsm4(stg + KH_OFF + off, h0, h1, h2, h3);
                ldsm4(stg + KL_OFF + off, e0, e1, e2, e3);
                mma_f16(cb[2 * nb],     qh[kk][0], qh[kk][1], qh[kk][2], qh[kk][3], h0, h1);
                mma_f16(cb[2 * nb + 1], qh[kk][0], qh[kk][1], qh[kk][2], qh[kk][3], h2, h3);
                mma_f16(cb[2 * nb],     qh[kk][0], qh[kk][1], qh[kk][2], qh[kk][3], e0, e1);
                mma_f16(cb[2 * nb + 1], qh[kk][0], qh[kk][1], qh[kk][2], qh[kk][3], e2, e3);
                mma_f16(cb[2 * nb],     ql[kk][0], ql[kk][1], ql[kk][2], ql[kk][3], h0, h1);
                mma_f16(cb[2 * nb + 1], ql[kk][0], ql[kk][1], ql[kk][2], ql[kk][3], h2, h3);
            }
        }

        // ---- softmax(A) — overlaps QK(B) drain ----
        {
            float mt0 = -INFINITY, mt1 = -INFINITY;
            #pragma unroll
            for (int nt = 0; nt < 8; ++nt) {
                mt0 = fmaxf(mt0, fmaxf(ca[nt][0], ca[nt][1]));
                mt1 = fmaxf(mt1, fmaxf(ca[nt][2], ca[nt][3]));
            }
            mt0 = fmaxf(mt0, __shfl_xor_sync(0xffffffffu, mt0, 1));
            mt0 = fmaxf(mt0, __shfl_xor_sync(0xffffffffu, mt0, 2));
            mt1 = fmaxf(mt1, __shfl_xor_sync(0xffffffffu, mt1, 1));
            mt1 = fmaxf(mt1, __shfl_xor_sync(0xffffffffu, mt1, 2));

            const float mn0 = fmaxf(m0, mt0);
            const float mn1 = fmaxf(m1, mt1);
            const float sc0 = ex2(m0 - mn0);   // first tile: ex2(-inf) = 0
            const float sc1 = ex2(m1 - mn1);
            m0 = mn0; m1 = mn1;

            uint32_t p[8][2];
            float lp0 = 0.0f, lp1 = 0.0f;
            #pragma unroll
            for (int nt = 0; nt < 8; ++nt) {
                const float e00 = ex2(ca[nt][0] - mn0);
                const float e01 = ex2(ca[nt][1] - mn0);
                const float e10 = ex2(ca[nt][2] - mn1);
                const float e11 = ex2(ca[nt][3] - mn1);
                lp0 += e00 + e01;
                lp1 += e10 + e11;
                __half2 h20 = __floats2half2_rn(e00, e01);
                __half2 h21 = __floats2half2_rn(e10, e11);
                p[nt][0] = *reinterpret_cast<uint32_t*>(&h20);
                p[nt][1] = *reinterpret_cast<uint32_t*>(&h21);
            }
            l0 = l0 * sc0 + lp0;
            l1 = l1 * sc1 + lp1;
            #pragma unroll
            for (int nt = 0; nt < 16; ++nt) {
                o[nt][0] *= sc0; o[nt][1] *= sc0;
                o[nt][2] *= sc1; o[nt][3] *= sc1;
            }

            // ---- PV(A): kv rows 0..63 ----
            #pragma unroll
            for (int kk2 = 0; kk2 < 4; ++kk2) {
                const uint32_t a0 = p[2 * kk2][0];
                const uint32_t a1 = p[2 * kk2][1];
                const uint32_t a2 = p[2 * kk2 + 1][0];
                const uint32_t a3 = p[2 * kk2 + 1][1];
                #pragma unroll
                for (int nn2 = 0; nn2 < 8; ++nn2) {
                    uint32_t va = stg + SV_OFF +
                        ((kk2 * 16 + (grp & 1) * 8 + lr) * VS
                         + (nn2 * 2 + (grp >> 1)) * 8) * 2;
                    uint32_t v0, v1, v2, v3;
                    ldsm4t(va, v0, v1, v2, v3);
                    mma_f16(o[2 * nn2],     a0, a1, a2, a3, v0, v1);
                    mma_f16(o[2 * nn2 + 1], a0, a1, a2, a3, v2, v3);
                }
            }
        }

        // ---- softmax(B) — overlaps PV(A) drain ----
        {
            float mt0 = -INFINITY, mt1 = -INFINITY;
            #pragma unroll
            for (int nt = 0; nt < 8; ++nt) {
                mt0 = fmaxf(mt0, fmaxf(cb[nt][0], cb[nt][1]));
                mt1 = fmaxf(mt1, fmaxf(cb[nt][2], cb[nt][3]));
            }
            mt0 = fmaxf(mt0, __shfl_xor_sync(0xffffffffu, mt0, 1));
            mt0 = fmaxf(mt0, __shfl_xor_sync(0xffffffffu, mt0, 2));
            mt1 = fmaxf(mt1, __shfl_xor_sync(0xffffffffu, mt1, 1));
            mt1 = fmaxf(mt1, __shfl_xor_sync(0xffffffffu, mt1, 2));

            const float mn0 = fmaxf(m0, mt0);
            const float mn1 = fmaxf(m1, mt1);
            const float sc0 = ex2(m0 - mn0);
            const float sc1 = ex2(m1 - mn1);
            m0 = mn0; m1 = mn1;

            uint32_t p[8][2];
            float lp0 = 0.0f, lp1 = 0.0f;
            #pragma unroll
            for (int nt = 0; nt < 8; ++nt) {
                const float e00 = ex2(cb[nt][0] - mn0);
                const float e01 = ex2(cb[nt][1] - mn0);
                const float e10 = ex2(cb[nt][2] - mn1);
                const float e11 = ex2(cb[nt][3] - mn1);
                lp0 += e00 + e01;
                lp1 += e10 + e11;
                __half2 h20 = __floats2half2_rn(e00, e01);
                __half2 h21 = __floats2half2_rn(e10, e11);
                p[nt][0] = *reinterpret_cast<uint32_t*>(&h20);
                p[nt][1] = *reinterpret_cast<uint32_t*>(&h21);
            }
            l0 = l0 * sc0 + lp0;
            l1 = l1 * sc1 + lp1;
            #pragma unroll
            for (int nt = 0; nt < 16; ++nt) {
                o[nt][0] *= sc0; o[nt][1] *= sc0;
                o[nt][2] *= sc1; o[nt][3] *= sc1;
            }

            // ---- PV(B): kv rows 64..127 ----
            #pragma unroll
            for (int kk2 = 4; kk2 < 8; ++kk2) {
                const int kb = kk2 - 4;
                const uint32_t a0 = p[2 * kb][0];
                const uint32_t a1 = p[2 * kb][1];
                const uint32_t a2 = p[2 * kb + 1][0];
                const uint32_t a3 = p[2 * kb + 1][1];
                #pragma unroll
                for (int nn2 = 0; nn2 < 8; ++nn2) {
                    uint32_t va = stg + SV_OFF +
                        ((kk2 * 16 + (grp & 1) * 8 + lr) * VS
                         + (nn2 * 2 + (grp >> 1)) * 8) * 2;
                    uint32_t v0, v1, v2, v3;
                    ldsm4t(va, v0, v1, v2, v3);
                    mma_f16(o[2 * nn2],     a0, a1, a2, a3, v0, v1);
                    mma_f16(o[2 * nn2 + 1], a0, a1, a2, a3, v2, v3);
                }
            }
        }
        __syncthreads();
    }

    l0 += __shfl_xor_sync(0xffffffffu, l0, 1);
    l0 += __shfl_xor_sync(0xffffffffu, l0, 2);
    l1 += __shfl_xor_sync(0xffffffffu, l1, 1);
    l1 += __shfl_xor_sync(0xffffffffu, l1, 2);
    const float inv0 = 1.0f / l0;
    const float inv1 = 1.0f / l1;

    #pragma unroll
    for (int nt = 0; nt < 16; ++nt) {
        float2 w0 = make_float2(o[nt][0] * inv0, o[nt][1] * inv0);
        float2 w1 = make_float2(o[nt][2] * inv1, o[nt][3] * inv1);
        *reinterpret_cast<float2*>(&outb[(size_t)(wbase + g) * FDIM + nt * 8 + 2 * tig]) = w0;
        *reinterpret_cast<float2*>(&outb[(size_t)(wbase + g + 8) * FDIM + nt * 8 + 2 * tig]) = w1;
    }
}

// ---------------------------------------------------------------------------
// Tensor-core projections, single pass: x tile split hi/lo ONCE, all three
// weight matrices resident in smem, K/Q/V computed sequentially.
// grid = (MROWS/128, 1). K,Q: 3-term compensated product, hi/lo outputs
// (Q scaled by log2e). V: 2-term (full x, w hi), fp16 output.
// ---------------------------------------------------------------------------
#define PXS 136                                  // half stride (272 B rows)
#define PXH_OFF 0
#define PXL_OFF 34816
#define WKH_OFF 69632
#define WKL_OFF (WKH_OFF + 17408)                // 87040
#define WQH_OFF (WKL_OFF + 17408)                // 104448
#define WQL_OFF (WQH_OFF + 17408)                // 121856
#define WVH_OFF (WQL_OFF + 17408)                // 139264
#define PROJ_SMEM (WVH_OFF + 34816)              // 174080

__global__ __launch_bounds__(256, 1) void proj_mma_kernel(
    const float* __restrict__ x,
    const float* __restrict__ wk,
    const float* __restrict__ wq,
    const float* __restrict__ wv,
    __half* __restrict__ Kh, __half* __restrict__ Kl,
    __half* __restrict__ Qh, __half* __restrict__ Ql,
    __half* __restrict__ Vh) {
    extern __shared__ char ps[];
    const uint32_t sb = cvta_s(ps);
    const int tid = threadIdx.x;
    const int lane = tid & 31;
    const int g = lane >> 2;
    const int tig = lane & 3;
    const int grp = lane >> 3;
    const int lr = lane & 7;
    const int wbase = (tid >> 5) * 16;
    const int row0 = blockIdx.x * 128;

    // Load + split x tile [128][128] fp32 -> hi/lo fp16 (once)
    #pragma unroll
    for (int i = 0; i < 16; ++i) {
        int e = i * 256 + tid;
        int r = e >> 5;
        int c4 = (e & 31) * 4;
        float4 v = *reinterpret_cast<const float4*>(&x[(size_t)(row0 + r) * 128 + c4]);
        __half hx = __float2half_rn(v.x), hy = __float2half_rn(v.y);
        __half hz = __float2half_rn(v.z), hw = __float2half_rn(v.w);
        char* dh = ps + PXH_OFF + ((size_t)r * PXS + c4) * 2;
        char* dl = ps + PXL_OFF + ((size_t)r * PXS + c4) * 2;
        *reinterpret_cast<__half2*>(dh)     = __halves2half2(hx, hy);
        *reinterpret_cast<__half2*>(dh + 4) = __halves2half2(hz, hw);
        *reinterpret_cast<__half2*>(dl) = __halves2half2(
            __float2half_rn(v.x - __half2float(hx)),
            __float2half_rn(v.y - __half2float(hy)));
        *reinterpret_cast<__half2*>(dl + 4) = __halves2half2(
            __float2half_rn(v.z - __half2float(hz)),
            __float2half_rn(v.w - __half2float(hw)));
    }
    // wk, wq transposed + split hi/lo; wv transposed hi only
    #pragma unroll 4
    for (int e = tid; e < 128 * 64; e += 256) {
        int k = e >> 6, n = e & 63;
        float v = wk[(size_t)k * 64 + n];
        __half hi = __float2half_rn(v);
        *reinterpret_cast<__half*>(ps + WKH_OFF + ((size_t)n * PXS + k) * 2) = hi;
        *reinterpret_cast<__half*>(ps + WKL_OFF + ((size_t)n * PXS + k) * 2) =
            __float2half_rn(v - __half2float(hi));
        float vq = wq[(size_t)k * 64 + n];
        __half hq = __float2half_rn(vq);
        *reinterpret_cast<__half*>(ps + WQH_OFF + ((size_t)n * PXS + k) * 2) = hq;
        *reinterpret_cast<__half*>(ps + WQL_OFF + ((size_t)n * PXS + k) * 2) =
            __float2half_rn(vq - __half2float(hq));
    }
    #pragma unroll 8
    for (int e = tid; e < 128 * 128; e += 256) {
        int k = e >> 7, n = e & 127;
        *reinterpret_cast<__half*>(ps + WVH_OFF + ((size_t)n * PXS + k) * 2) =
            __float2half_rn(wv[(size_t)k * 128 + n]);
    }
    __syncthreads();

    // A-frags (x hi/lo), 8 k-steps — held for all three GEMMs
    uint32_t ah[8][4], al[8][4];
    #pragma unroll
    for (int kk = 0; kk < 8; ++kk) {
        uint32_t a = sb + PXH_OFF +
            ((wbase + lr + (grp & 1) * 8) * PXS + kk * 16 + (grp >> 1) * 8) * 2;
        ldsm4(a, ah[kk][0], ah[kk][1], ah[kk][2], ah[kk][3]);
        ldsm4(a + (PXL_OFF - PXH_OFF), al[kk][0], al[kk][1], al[kk][2], al[kk][3]);
    }

    // ---- K and Q: N=64, 3-term compensated product ----
    #pragma unroll
    for (int which = 0; which < 2; ++which) {
        const uint32_t wh_off = (which == 0) ? WKH_OFF : WQH_OFF;
        const uint32_t wl_off = (which == 0) ? WKL_OFF : WQL_OFF;

        float c[8][4];
        #pragma unroll
        for (int nt = 0; nt < 8; ++nt)
            #pragma unroll
            for (int j = 0; j < 4; ++j) c[nt][j] = 0.0f;

        #pragma unroll
        for (int kk = 0; kk < 8; ++kk) {
            #pragma unroll
            for (int nn2 = 0; nn2 < 4; ++nn2) {
                uint32_t off = (((nn2 * 2 + (grp >> 1)) * 8 + lr) * PXS
                                + kk * 16 + (grp & 1) * 8) * 2;
                uint32_t h0, h1, h2, h3, e0, e1, e2, e3;
                ldsm4(sb + wh_off + off, h0, h1, h2, h3);
                ldsm4(sb + wl_off + off, e0, e1, e2, e3);
                mma_f16(c[2 * nn2],     ah[kk][0], ah[kk][1], ah[kk][2], ah[kk][3], h0, h1);
                mma_f16(c[2 * nn2 + 1], ah[kk][0], ah[kk][1], ah[kk][2], ah[kk][3], h2, h3);
                mma_f16(c[2 * nn2],     ah[kk][0], ah[kk][1], ah[kk][2], ah[kk][3], e0, e1);
                mma_f16(c[2 * nn2 + 1], ah[kk][0], ah[kk][1], ah[kk][2], ah[kk][3], e2, e3);
                mma_f16(c[2 * nn2],     al[kk][0], al[kk][1], al[kk][2], al[kk][3], h0, h1);
                mma_f16(c[2 * nn2 + 1], al[kk][0], al[kk][1], al[kk][2], al[kk][3], h2, h3);
            }
        }

        const float scale = (which == 1) ? LOG2E : 1.0f;  // fold log2e into Q
        __half* Hh = (which == 0) ? Kh : Qh;
        __half* Hl = (which == 0) ? Kl : Ql;
        #pragma unroll
        for (int nt = 0; nt < 8; ++nt) {
            const int col = nt * 8 + 2 * tig;
            #pragma unroll
            for (int half_m = 0; half_m < 2; ++half_m) {
                const size_t idx =
                    (size_t)(row0 + wbase + g + half_m * 8) * WDIM + col;
                const float v0 = c[nt][2 * half_m] * scale;
                const float v1 = c[nt][2 * half_m + 1] * scale;
                const __half h0 = __float2half_rn(v0);
                const __half h1 = __float2half_rn(v1);
                *reinterpret_cast<__half2*>(&Hh[idx]) = __halves2half2(h0, h1);
                *reinterpret_cast<__half2*>(&Hl[idx]) = __halves2half2(
                    __float2half_rn(v0 - __half2float(h0)),
                    __float2half_rn(v1 - __half2float(h1)));
            }
        }
    }

    // ---- V: N=128, 2-term (x hi+lo, w hi) ----
    {
        float c[16][4];
        #pragma unroll
        for (int nt = 0; nt < 16; ++nt)
            #pragma unroll
            for (int j = 0; j < 4; ++j) c[nt][j] = 0.0f;

        #pragma unroll
        for (int kk = 0; kk < 8; ++kk) {
            #pragma unroll
            for (int nn2 = 0; nn2 < 8; ++nn2) {
                uint32_t off = (((nn2 * 2 + (grp >> 1)) * 8 + lr) * PXS
                                + kk * 16 + (grp & 1) * 8) * 2;
                uint32_t h0, h1, h2, h3;
                ldsm4(sb + WVH_OFF + off, h0, h1, h2, h3);
                mma_f16(c[2 * nn2],     ah[kk][0], ah[kk][1], ah[kk][2], ah[kk][3], h0, h1);
                mma_f16(c[2 * nn2 + 1], ah[kk][0], ah[kk][1], ah[kk][2], ah[kk][3], h2, h3);
                mma_f16(c[2 * nn2],     al[kk][0], al[kk][1], al[kk][2], al[kk][3], h0, h1);
                mma_f16(c[2 * nn2 + 1], al[kk][0], al[kk][1], al[kk][2], al[kk][3], h2, h3);
            }
        }

        #pragma unroll
        for (int nt = 0; nt < 16; ++nt) {
            const int col = nt * 8 + 2 * tig;
            #pragma unroll
            for (int half_m = 0; half_m < 2; ++half_m) {
                const size_t idx =
                    (size_t)(row0 + wbase + g + half_m * 8) * FDIM + col;
                *reinterpret_cast<__half2*>(&Vh[idx]) = __halves2half2(
                    __float2half_rn(c[nt][2 * half_m]),
                    __float2half_rn(c[nt][2 * half_m + 1]));
            }
        }
    }
}

// ---------------------------------------------------------------------------
extern "C" void kernel_launch(void* const* d_in, const int* in_sizes, int n_in,
                              void* d_out, int out_size) {
    const float* x  = (const float*)d_in[0];
    // d_in[1] = adj (bool), unused by the reference math
    const float* wk = (const float*)d_in[2];
    const float* wv = (const float*)d_in[3];
    const float* wq = (const float*)d_in[4];
    float* out = (float*)d_out;

    void *pQh, *pQl, *pKh, *pKl, *pVh;
    cudaGetSymbolAddress(&pQh, g_Qh);
    cudaGetSymbolAddress(&pQl, g_Ql);
    cudaGetSymbolAddress(&pKh, g_Kh);
    cudaGetSymbolAddress(&pKl, g_Kl);
    cudaGetSymbolAddress(&pVh, g_Vh);

    cudaFuncSetAttribute(attn_mma_kernel,
                         cudaFuncAttributeMaxDynamicSharedMemorySize, ATTN_SMEM);
    cudaFuncSetAttribute(proj_mma_kernel,
                         cudaFuncAttributeMaxDynamicSharedMemorySize, PROJ_SMEM);

    proj_mma_kernel<<<dim3(MROWS / 128, 1), 256, PROJ_SMEM>>>(
        x, wk, wq, wv,
        (__half*)pKh, (__half*)pKl, (__half*)pQh, (__half*)pQl, (__half*)pVh);

    attn_mma_kernel<<<dim3(SEQ / 128, BATCH), 256, ATTN_SMEM>>>(
        (const __half*)pQh, (const __half*)pQl,
        (const __half*)pKh, (const __half*)pKl,
        (const __half*)pVh, out);
}